// round 7
// baseline (speedup 1.0000x reference)
#include <cuda_runtime.h>
#include <math.h>

#define BS 128
#define T  32
#define DH 128
#define NS 512
#define EPSF 1e-8f
#define NT 1024

// dynamic smem: staged weights (floats)
#define W_HH_OFF 0
#define W_RH_OFF 16384
#define W_R_OFF  32768
#define DYN_FLOATS (32768 + 17152)          // Whh + Wrh + Wr(128x134)
#define DYN_BYTES  (DYN_FLOATS * 4)         // 199680

// mem layout: g_mem[b][n][j]
__device__ float g_mem[BS*NS*DH];     // 33.5 MB
__device__ float g_xW [T*BS*DH];      // x@Wxh + bh, [t][b][i]
__device__ float g_hall[T*BS*DH];
__device__ float g_rall[T*BS*DH];

// ---------------- helpers ----------------
__device__ __forceinline__ float softplusf(float x) {
    return fmaxf(x, 0.f) + log1pf(expf(-fabsf(x)));
}
__device__ __forceinline__ float sigmoidf(float x) {
    return 1.f / (1.f + __expf(-x));
}

// ---------------- init (float4 stores) ----------------
__global__ void init_kernel() {
    int i = blockIdx.x * blockDim.x + threadIdx.x;
    int stride = gridDim.x * blockDim.x;
    float4 v = make_float4(1e-6f, 1e-6f, 1e-6f, 1e-6f);
    float4* m4 = reinterpret_cast<float4*>(g_mem);
    for (int k = i; k < BS*NS*DH/4; k += stride) m4[k] = v;
}

// ---------------- x @ Wxh + bh : 512 blocks x 128 thr, 8 rows/block ----------------
__global__ __launch_bounds__(128)
void xw_kernel(const float* __restrict__ x,
               const float* __restrict__ Wxh,
               const float* __restrict__ bh) {
    __shared__ float xs[8][DH];
    int r0  = blockIdx.x * 8;          // row = b*32 + t
    int tid = threadIdx.x;
    for (int idx = tid; idx < 8*DH; idx += 128)
        xs[idx >> 7][idx & 127] = x[(r0 + (idx >> 7)) * DH + (idx & 127)];
    __syncthreads();
    int j = tid;
    float acc[8];
    #pragma unroll
    for (int rr = 0; rr < 8; rr++) acc[rr] = 0.f;
    #pragma unroll 4
    for (int i = 0; i < DH; i++) {
        float w = Wxh[i * DH + j];
        #pragma unroll
        for (int rr = 0; rr < 8; rr++) acc[rr] += xs[rr][i] * w;
    }
    float bb = bh[j];
    #pragma unroll
    for (int rr = 0; rr < 8; rr++) {
        int row = r0 + rr;
        int b = row >> 5, t = row & 31;
        g_xW[(t * BS + b) * DH + j] = acc[rr] + bb;
    }
}

// ---------------- persistent fused sequence kernel ----------------
// grid BS blocks x 1024 threads; block b runs ALL T steps for batch b.
__global__ __launch_bounds__(NT, 1)
void seq_kernel(const float* __restrict__ Whh, const float* __restrict__ Wrh,
                const float* __restrict__ Wr,  const float* __restrict__ br,
                const float* __restrict__ Ww,  const float* __restrict__ bw) {
    extern __shared__ float dyn[];
    float* dWhh = dyn + W_HH_OFF;
    float* dWrh = dyn + W_RH_OFF;
    float* dWr  = dyn + W_R_OFF;

    __shared__ float s_h[DH], s_r[DH], s_hn[DH];
    __shared__ float osm[524];
    __shared__ __align__(16) float sh_kr[DH], sh_kw[DH];
    __shared__ float s_dr[NS], s_dw[NS], s_nrm[NS];
    __shared__ float s_wg[NS], s_wr[NS], s_ww[NS], s_wprev[NS];
    __shared__ float scratch[NT];
    __shared__ float s_par[12];
    __shared__ float s_kn[2];
    __shared__ float s_redR[2];         // read softmax: m, se (also reused for pow-sums)
    __shared__ float s_redW[2];         // write softmax: m, se

    int b    = blockIdx.x;
    int tid  = threadIdx.x;
    int lane = tid & 31, wid = tid >> 5;

    // --- stage weights into smem (once) + init state ---
    {
        const float4* s1 = (const float4*)Whh;  float4* d1 = (float4*)dWhh;
        const float4* s2 = (const float4*)Wrh;  float4* d2 = (float4*)dWrh;
        const float4* s3 = (const float4*)Wr;   float4* d3 = (float4*)dWr;
        for (int i = tid; i < 4096; i += NT) { d1[i] = s1[i]; d2[i] = s2[i]; }
        for (int i = tid; i < 4288; i += NT) d3[i] = s3[i];
    }
    if (tid < DH) { s_h[tid] = 0.f; s_r[tid] = 0.f; }
    if (tid < NS) s_wprev[tid] = 1.0f / (float)NS;
    __syncthreads();

    for (int t = 0; t < T; t++) {
        // ===== h = tanh(xW + h@Whh + r@Wrh), 8-way slice over jj =====
        {
            int j = tid & 127, sl = tid >> 7;
            float acc = 0.f;
            int j0 = sl * 16;
            #pragma unroll
            for (int q = 0; q < 16; q++) {
                int jj = j0 + q;
                acc += s_h[jj] * dWhh[jj*DH + j] + s_r[jj] * dWrh[jj*DH + j];
            }
            scratch[sl*DH + j] = acc;
        }
        __syncthreads();
        if (tid < DH) {
            float a = g_xW[(t*BS + b)*DH + tid];
            #pragma unroll
            for (int sl = 0; sl < 8; sl++) a += scratch[sl*DH + tid];
            float h = tanhf(a);
            s_hn[tid] = h;
            g_hall[(t*BS + b)*DH + tid] = h;
        }
        __syncthreads();

        // ===== o = h@[Wr|Ww] + bias =====
        {
            int col = tid & 511, half = tid >> 9;
            float acc = 0.f;
            int j0 = half * 64;
            if (col < 134) {
                #pragma unroll 8
                for (int q = 0; q < 64; q++) {
                    int jj = j0 + q;
                    acc += s_hn[jj] * dWr[jj*134 + col];
                }
            } else {
                int cc = col - 134;
                #pragma unroll 8
                for (int q = 0; q < 64; q++) {
                    int jj = j0 + q;
                    acc += s_hn[jj] * Ww[jj*390 + cc];
                }
            }
            scratch[tid] = acc;
        }
        if (tid < 12) {                    // tail cols: Ww cc 378..389
            int cc = 378 + tid;
            float acc = bw[cc];
            #pragma unroll 8
            for (int jj = 0; jj < DH; jj++) acc += s_hn[jj] * Ww[jj*390 + cc];
            osm[512 + tid] = acc;
        }
        __syncthreads();
        if (tid < 512) {
            float v = scratch[tid] + scratch[tid + 512];
            v += (tid < 134) ? br[tid] : bw[tid - 134];
            osm[tid] = v;
        }
        __syncthreads();

        // ===== activations =====
        if (tid < 128)       sh_kr[tid]       = osm[tid];
        else if (tid < 256)  sh_kw[tid - 128] = osm[tid + 6];
        else if (tid < 384)  osm[tid + 12]    = sigmoidf(osm[tid + 12]);   // e
        else if (tid < 512)  osm[tid + 12]    = tanhf(osm[tid + 12]);      // a
        else if (tid == 512) {
            s_par[0] = softplusf(osm[128]);
            s_par[1] = sigmoidf(osm[129]);
            {
                float v0 = osm[130], v1 = osm[131], v2 = osm[132];
                float m = fmaxf(v0, fmaxf(v1, v2));
                float e0 = __expf(v0-m), e1 = __expf(v1-m), e2 = __expf(v2-m);
                float s = e0 + e1 + e2;
                s_par[2] = e0/s; s_par[3] = e1/s; s_par[4] = e2/s;
            }
            s_par[5] = 1.0f + softplusf(osm[133]);
            s_par[6] = softplusf(osm[262]);
            s_par[7] = sigmoidf(osm[263]);
            {
                float v0 = osm[264], v1 = osm[265], v2 = osm[266];
                float m = fmaxf(v0, fmaxf(v1, v2));
                float e0 = __expf(v0-m), e1 = __expf(v1-m), e2 = __expf(v2-m);
                float s = e0 + e1 + e2;
                s_par[8] = e0/s; s_par[9] = e1/s; s_par[10] = e2/s;
            }
            s_par[11] = 1.0f + softplusf(osm[267]);
        }
        __syncthreads();

        // ===== key norms (warps 0,1) =====
        if (wid < 2) {
            const float* k = wid ? sh_kw : sh_kr;
            float s = 0.f;
            #pragma unroll
            for (int j = lane; j < DH; j += 32) { float a = k[j]; s += a*a; }
            #pragma unroll
            for (int o = 16; o; o >>= 1) s += __shfl_xor_sync(0xffffffffu, s, o);
            if (lane == 0) s_kn[wid] = sqrtf(s);
        }

        // ===== phase 1: dots + row norms (warp per row, 2 rows in flight) =====
        {
            float4 kr4 = reinterpret_cast<float4*>(sh_kr)[lane];
            float4 kw4 = reinterpret_cast<float4*>(sh_kw)[lane];
            const float4* memb = reinterpret_cast<const float4*>(g_mem + (size_t)b*NS*DH);
            for (int n0 = wid; n0 < NS; n0 += 64) {
                int n1 = n0 + 32;
                float4 v0 = memb[n0*32 + lane];
                float4 v1 = memb[n1*32 + lane];
                float dr0 = v0.x*kr4.x + v0.y*kr4.y + v0.z*kr4.z + v0.w*kr4.w;
                float dw0 = v0.x*kw4.x + v0.y*kw4.y + v0.z*kw4.z + v0.w*kw4.w;
                float ss0 = v0.x*v0.x + v0.y*v0.y + v0.z*v0.z + v0.w*v0.w;
                float dr1 = v1.x*kr4.x + v1.y*kr4.y + v1.z*kr4.z + v1.w*kr4.w;
                float dw1 = v1.x*kw4.x + v1.y*kw4.y + v1.z*kw4.z + v1.w*kw4.w;
                float ss1 = v1.x*v1.x + v1.y*v1.y + v1.z*v1.z + v1.w*v1.w;
                #pragma unroll
                for (int o = 16; o; o >>= 1) {
                    dr0 += __shfl_xor_sync(0xffffffffu, dr0, o);
                    dw0 += __shfl_xor_sync(0xffffffffu, dw0, o);
                    ss0 += __shfl_xor_sync(0xffffffffu, ss0, o);
                    dr1 += __shfl_xor_sync(0xffffffffu, dr1, o);
                    dw1 += __shfl_xor_sync(0xffffffffu, dw1, o);
                    ss1 += __shfl_xor_sync(0xffffffffu, ss1, o);
                }
                if (lane == 0) {
                    s_dr[n0] = dr0; s_dw[n0] = dw0; s_nrm[n0] = sqrtf(ss0);
                    s_dr[n1] = dr1; s_dw[n1] = dw1; s_nrm[n1] = sqrtf(ss1);
                }
            }
        }
        __syncthreads();

        int n = tid;
        bool act = (tid < NS);

        // ===== both logits, then parallel softmax stats (warp0=read, warp1=write) =====
        float cr = 0.f, cw = 0.f;
        if (act) {
            float inv = 1.f / s_nrm[n];
            cr = s_par[0] * s_dr[n] / (s_nrm[n] * s_kn[0] + EPSF);
            cw = s_par[6] * s_dw[n] / (s_nrm[n] * s_kn[1] + EPSF);
            s_dr[n] = cr; s_dw[n] = cw;
            (void)inv;
        }
        __syncthreads();
        if (wid == 0) {                       // read: max + exp-sum
            float vals[16], m = -INFINITY;
            #pragma unroll
            for (int k = 0; k < 16; k++) { vals[k] = s_dr[lane + k*32]; m = fmaxf(m, vals[k]); }
            #pragma unroll
            for (int o = 16; o; o >>= 1) m = fmaxf(m, __shfl_xor_sync(0xffffffffu, m, o));
            float se = 0.f;
            #pragma unroll
            for (int k = 0; k < 16; k++) se += __expf(vals[k] - m);
            #pragma unroll
            for (int o = 16; o; o >>= 1) se += __shfl_xor_sync(0xffffffffu, se, o);
            if (lane == 0) { s_redR[0] = m; s_redR[1] = se; }
        } else if (wid == 1) {                // write: max + exp-sum
            float vals[16], m = -INFINITY;
            #pragma unroll
            for (int k = 0; k < 16; k++) { vals[k] = s_dw[lane + k*32]; m = fmaxf(m, vals[k]); }
            #pragma unroll
            for (int o = 16; o; o >>= 1) m = fmaxf(m, __shfl_xor_sync(0xffffffffu, m, o));
            float se = 0.f;
            #pragma unroll
            for (int k = 0; k < 16; k++) se += __expf(vals[k] - m);
            #pragma unroll
            for (int o = 16; o; o >>= 1) se += __shfl_xor_sync(0xffffffffu, se, o);
            if (lane == 0) { s_redW[0] = m; s_redW[1] = se; }
        }
        __syncthreads();

        // ===== read attention: gate, shift, sharpen =====
        {
            if (act) {
                float wc = __expf(cr - s_redR[0]) / s_redR[1];
                float gr = s_par[1];
                s_wg[n] = gr * wc + (1.f - gr) * s_wprev[n];
            }
            __syncthreads();
            float w = 0.f;
            if (act) {
                float wt = s_par[2] * s_wg[(n+1) & (NS-1)] + s_par[3] * s_wg[n]
                         + s_par[4] * s_wg[(n-1) & (NS-1)];
                w = __powf(wt, s_par[5]);
                scratch[n] = w;
            }
            __syncthreads();
            if (wid == 0) {
                float sw = 0.f;
                #pragma unroll
                for (int k = 0; k < 16; k++) sw += scratch[lane + k*32];
                #pragma unroll
                for (int o = 16; o; o >>= 1) sw += __shfl_xor_sync(0xffffffffu, sw, o);
                if (lane == 0) s_redR[0] = sw;
            }
            __syncthreads();
            if (act) s_wr[n] = w / (s_redR[0] + EPSF);
        }
        __syncthreads();

        // ===== write attention: gate (prev = w_r), shift, sharpen =====
        {
            if (act) {
                float wc = __expf(cw - s_redW[0]) / s_redW[1];
                float gw = s_par[7];
                s_wg[n] = gw * wc + (1.f - gw) * s_wr[n];
            }
            __syncthreads();
            float w = 0.f;
            if (act) {
                float wt = s_par[8] * s_wg[(n+1) & (NS-1)] + s_par[9] * s_wg[n]
                         + s_par[10] * s_wg[(n-1) & (NS-1)];
                w = __powf(wt, s_par[11]);
                scratch[n] = w;
            }
            __syncthreads();
            if (wid == 0) {
                float sw = 0.f;
                #pragma unroll
                for (int k = 0; k < 16; k++) sw += scratch[lane + k*32];
                #pragma unroll
                for (int o = 16; o; o >>= 1) sw += __shfl_xor_sync(0xffffffffu, sw, o);
                if (lane == 0) s_redR[0] = sw;
            }
            __syncthreads();
            if (act) {
                float ww = w / (s_redR[0] + EPSF);
                s_ww[n] = ww;
                s_wprev[n] = ww;
            }
        }
        __syncthreads();

        // ===== phase F: r = w_r . mem(old) + mem update; thread=col j, 8 n-chunks =====
        {
            int j = tid & 127, ch = tid >> 7;       // 8 chunks of 64 slots
            float e_j = osm[268 + j];
            float a_j = osm[396 + j];
            float* mb = g_mem + (size_t)b*NS*DH;
            float racc = 0.f;
            int nb = ch * 64;
            #pragma unroll 8
            for (int q = 0; q < 64; q++) {
                int nn = nb + q;
                float v = mb[nn*DH + j];
                racc = fmaf(s_wr[nn], v, racc);
                float wwn = s_ww[nn];
                mb[nn*DH + j] = fmaf(wwn, fmaf(-e_j, v, a_j), v);
            }
            scratch[ch*DH + j] = racc;
        }
        __syncthreads();
        if (tid < DH) {
            float r = 0.f;
            #pragma unroll
            for (int ch = 0; ch < 8; ch++) r += scratch[ch*DH + tid];
            s_r[tid] = r;
            g_rall[(t*BS + b)*DH + tid] = r;
            s_h[tid] = s_hn[tid];
        }
        __syncthreads();
    }
}

// ---------------- deferred output GEMM: 512 blocks x 128 thr, 8 rows/block ----------------
__global__ __launch_bounds__(128)
void y_kernel(const float* __restrict__ Wout,
              const float* __restrict__ bout,
              float* __restrict__ out) {
    __shared__ float sh[8][DH], sr[8][DH];
    int r0  = blockIdx.x * 8;          // row = t*BS + b
    int tid = threadIdx.x;
    for (int idx = tid; idx < 8*DH; idx += 128) {
        int rr = idx >> 7, i = idx & 127;
        sh[rr][i] = g_hall[(r0 + rr)*DH + i];
        sr[rr][i] = g_rall[(r0 + rr)*DH + i];
    }
    __syncthreads();
    int j = tid;
    float acc[8];
    #pragma unroll
    for (int rr = 0; rr < 8; rr++) acc[rr] = 0.f;
    #pragma unroll 4
    for (int i = 0; i < DH; i++) {
        float w1 = Wout[i * DH + j];
        float w2 = Wout[(DH + i) * DH + j];
        #pragma unroll
        for (int rr = 0; rr < 8; rr++) acc[rr] += sh[rr][i] * w1 + sr[rr][i] * w2;
    }
    float bb = bout[j];
    #pragma unroll
    for (int rr = 0; rr < 8; rr++) {
        int row = r0 + rr;                 // row = t*BS + b
        int tt = row >> 7, bb2 = row & 127;
        out[(bb2 * T + tt) * DH + j] = acc[rr] + bb;
    }
}

// ---------------- launch ----------------
extern "C" void kernel_launch(void* const* d_in, const int* in_sizes, int n_in,
                              void* d_out, int out_size) {
    const float* x    = (const float*)d_in[0];
    const float* Wxh  = (const float*)d_in[1];
    const float* Whh  = (const float*)d_in[2];
    const float* Wrh  = (const float*)d_in[3];
    const float* bh   = (const float*)d_in[4];
    const float* Wout = (const float*)d_in[5];
    const float* bout = (const float*)d_in[6];
    const float* Wr   = (const float*)d_in[7];
    const float* br   = (const float*)d_in[8];
    const float* Ww   = (const float*)d_in[9];
    const float* bw   = (const float*)d_in[10];
    float* out = (float*)d_out;

    // opt-in to large dynamic smem (non-stream API; graph-capture safe, idempotent)
    cudaFuncSetAttribute(seq_kernel, cudaFuncAttributeMaxDynamicSharedMemorySize, DYN_BYTES);

    init_kernel<<<1024, 256>>>();
    xw_kernel<<<(BS*T)/8, 128>>>(x, Wxh, bh);
    seq_kernel<<<BS, NT, DYN_BYTES>>>(Whh, Wrh, Wr, br, Ww, bw);
    y_kernel<<<(BS*T)/8, 128>>>(Wout, bout, out);
}

// round 9
// speedup vs baseline: 1.5730x; 1.5730x over previous
#include <cuda_runtime.h>
#include <math.h>

#define BS 128
#define T  32
#define DH 128
#define NS 512
#define EPSF 1e-8f
#define NT 1024

// dynamic smem: staged weights (floats)
#define W_HH_OFF 0
#define W_RH_OFF 16384
#define W_R_OFF  32768
#define DYN_FLOATS (32768 + 17152)          // Whh + Wrh + Wr(128x134)
#define DYN_BYTES  (DYN_FLOATS * 4)         // 199680

// mem layout: g_mem[b][n][j]
__device__ float g_mem[BS*NS*DH];     // 33.5 MB
__device__ float g_xW [T*BS*DH];      // x@Wxh + bh, [t][b][i]
__device__ float g_hall[T*BS*DH];
__device__ float g_rall[T*BS*DH];

// ---------------- helpers ----------------
__device__ __forceinline__ float softplusf(float x) {
    return fmaxf(x, 0.f) + log1pf(expf(-fabsf(x)));
}
__device__ __forceinline__ float sigmoidf(float x) {
    return 1.f / (1.f + __expf(-x));
}

// ---------------- init (float4 stores) ----------------
__global__ void init_kernel() {
    int i = blockIdx.x * blockDim.x + threadIdx.x;
    int stride = gridDim.x * blockDim.x;
    float4 v = make_float4(1e-6f, 1e-6f, 1e-6f, 1e-6f);
    float4* m4 = reinterpret_cast<float4*>(g_mem);
    for (int k = i; k < BS*NS*DH/4; k += stride) m4[k] = v;
}

// ---------------- x @ Wxh + bh : 256 blocks x 256 thr, 16 rows/block ----------------
__global__ __launch_bounds__(256)
void xw_kernel(const float* __restrict__ x,
               const float* __restrict__ Wxh,
               const float* __restrict__ bh) {
    __shared__ float xs[16][DH];
    int r0  = blockIdx.x * 16;         // row = b*32 + t
    int tid = threadIdx.x;
    for (int idx = tid; idx < 16*DH; idx += 256)
        xs[idx >> 7][idx & 127] = x[(r0 + (idx >> 7)) * DH + (idx & 127)];
    __syncthreads();
    int j = tid & 127, rg = tid >> 7;  // rg in {0,1}: rows rg*8 .. rg*8+7
    float acc[8];
    #pragma unroll
    for (int rr = 0; rr < 8; rr++) acc[rr] = 0.f;
    #pragma unroll 4
    for (int i = 0; i < DH; i++) {
        float w = Wxh[i * DH + j];
        #pragma unroll
        for (int rr = 0; rr < 8; rr++) acc[rr] += xs[rg*8 + rr][i] * w;
    }
    float bb = bh[j];
    #pragma unroll
    for (int rr = 0; rr < 8; rr++) {
        int row = r0 + rg*8 + rr;
        int b = row >> 5, t = row & 31;
        g_xW[(t * BS + b) * DH + j] = acc[rr] + bb;
    }
}

// ---------------- persistent fused sequence kernel (R6 body, 779us-verified) ----------------
// grid BS blocks x 1024 threads; block b runs ALL T steps for batch b.
__global__ __launch_bounds__(NT, 1)
void seq_kernel(const float* __restrict__ Whh, const float* __restrict__ Wrh,
                const float* __restrict__ Wr,  const float* __restrict__ br,
                const float* __restrict__ Ww,  const float* __restrict__ bw) {
    extern __shared__ float dyn[];
    float* dWhh = dyn + W_HH_OFF;
    float* dWrh = dyn + W_RH_OFF;
    float* dWr  = dyn + W_R_OFF;

    __shared__ float s_h[DH], s_r[DH], s_hn[DH];
    __shared__ float osm[524];
    __shared__ __align__(16) float sh_kr[DH], sh_kw[DH];
    __shared__ float s_dr[NS], s_dw[NS], s_nrm[NS];
    __shared__ float s_wg[NS], s_wr[NS], s_ww[NS], s_wprev[NS];
    __shared__ float scratch[NT];
    __shared__ float s_par[12];
    __shared__ float s_kn[2];
    __shared__ float s_red[2];          // m, se / sw

    int b    = blockIdx.x;
    int tid  = threadIdx.x;
    int lane = tid & 31, wid = tid >> 5;

    // --- stage weights into smem (once) + init state ---
    {
        const float4* s1 = (const float4*)Whh;  float4* d1 = (float4*)dWhh;
        const float4* s2 = (const float4*)Wrh;  float4* d2 = (float4*)dWrh;
        const float4* s3 = (const float4*)Wr;   float4* d3 = (float4*)dWr;
        for (int i = tid; i < 4096; i += NT) { d1[i] = s1[i]; d2[i] = s2[i]; }
        for (int i = tid; i < 4288; i += NT) d3[i] = s3[i];
    }
    if (tid < DH) { s_h[tid] = 0.f; s_r[tid] = 0.f; }
    if (tid < NS) s_wprev[tid] = 1.0f / (float)NS;
    __syncthreads();

    for (int t = 0; t < T; t++) {
        // ===== h = tanh(xW + h@Whh + r@Wrh), 8-way slice over jj =====
        {
            int j = tid & 127, sl = tid >> 7;
            float acc = 0.f;
            int j0 = sl * 16;
            #pragma unroll
            for (int q = 0; q < 16; q++) {
                int jj = j0 + q;
                acc += s_h[jj] * dWhh[jj*DH + j] + s_r[jj] * dWrh[jj*DH + j];
            }
            scratch[sl*DH + j] = acc;
        }
        __syncthreads();
        if (tid < DH) {
            float a = g_xW[(t*BS + b)*DH + tid];
            #pragma unroll
            for (int sl = 0; sl < 8; sl++) a += scratch[sl*DH + tid];
            float h = tanhf(a);
            s_hn[tid] = h;
            g_hall[(t*BS + b)*DH + tid] = h;
        }
        __syncthreads();

        // ===== o = h@[Wr|Ww] + bias =====
        {
            int col = tid & 511, half = tid >> 9;
            float acc = 0.f;
            int j0 = half * 64;
            if (col < 134) {
                #pragma unroll 8
                for (int q = 0; q < 64; q++) {
                    int jj = j0 + q;
                    acc += s_hn[jj] * dWr[jj*134 + col];
                }
            } else {
                int cc = col - 134;
                #pragma unroll 8
                for (int q = 0; q < 64; q++) {
                    int jj = j0 + q;
                    acc += s_hn[jj] * Ww[jj*390 + cc];
                }
            }
            scratch[tid] = acc;
        }
        if (tid < 12) {                    // tail cols: Ww cc 378..389
            int cc = 378 + tid;
            float acc = bw[cc];
            #pragma unroll 8
            for (int jj = 0; jj < DH; jj++) acc += s_hn[jj] * Ww[jj*390 + cc];
            osm[512 + tid] = acc;
        }
        __syncthreads();
        if (tid < 512) {
            float v = scratch[tid] + scratch[tid + 512];
            v += (tid < 134) ? br[tid] : bw[tid - 134];
            osm[tid] = v;
        }
        __syncthreads();

        // ===== activations =====
        if (tid < 128)       sh_kr[tid]       = osm[tid];
        else if (tid < 256)  sh_kw[tid - 128] = osm[tid + 6];
        else if (tid < 384)  osm[tid + 12]    = sigmoidf(osm[tid + 12]);   // e
        else if (tid < 512)  osm[tid + 12]    = tanhf(osm[tid + 12]);      // a
        else if (tid == 512) {
            s_par[0] = softplusf(osm[128]);
            s_par[1] = sigmoidf(osm[129]);
            {
                float v0 = osm[130], v1 = osm[131], v2 = osm[132];
                float m = fmaxf(v0, fmaxf(v1, v2));
                float e0 = __expf(v0-m), e1 = __expf(v1-m), e2 = __expf(v2-m);
                float s = e0 + e1 + e2;
                s_par[2] = e0/s; s_par[3] = e1/s; s_par[4] = e2/s;
            }
            s_par[5] = 1.0f + softplusf(osm[133]);
            s_par[6] = softplusf(osm[262]);
            s_par[7] = sigmoidf(osm[263]);
            {
                float v0 = osm[264], v1 = osm[265], v2 = osm[266];
                float m = fmaxf(v0, fmaxf(v1, v2));
                float e0 = __expf(v0-m), e1 = __expf(v1-m), e2 = __expf(v2-m);
                float s = e0 + e1 + e2;
                s_par[8] = e0/s; s_par[9] = e1/s; s_par[10] = e2/s;
            }
            s_par[11] = 1.0f + softplusf(osm[267]);
        }
        __syncthreads();

        // ===== key norms (warps 0,1) =====
        if (wid < 2) {
            const float* k = wid ? sh_kw : sh_kr;
            float s = 0.f;
            #pragma unroll
            for (int j = lane; j < DH; j += 32) { float a = k[j]; s += a*a; }
            #pragma unroll
            for (int o = 16; o; o >>= 1) s += __shfl_xor_sync(0xffffffffu, s, o);
            if (lane == 0) s_kn[wid] = sqrtf(s);
        }

        // ===== phase 1: dots + row norms (warp per row, 2 rows in flight) =====
        {
            float4 kr4 = reinterpret_cast<float4*>(sh_kr)[lane];
            float4 kw4 = reinterpret_cast<float4*>(sh_kw)[lane];
            const float4* memb = reinterpret_cast<const float4*>(g_mem + (size_t)b*NS*DH);
            for (int n0 = wid; n0 < NS; n0 += 64) {
                int n1 = n0 + 32;
                float4 v0 = memb[n0*32 + lane];
                float4 v1 = memb[n1*32 + lane];
                float dr0 = v0.x*kr4.x + v0.y*kr4.y + v0.z*kr4.z + v0.w*kr4.w;
                float dw0 = v0.x*kw4.x + v0.y*kw4.y + v0.z*kw4.z + v0.w*kw4.w;
                float ss0 = v0.x*v0.x + v0.y*v0.y + v0.z*v0.z + v0.w*v0.w;
                float dr1 = v1.x*kr4.x + v1.y*kr4.y + v1.z*kr4.z + v1.w*kr4.w;
                float dw1 = v1.x*kw4.x + v1.y*kw4.y + v1.z*kw4.z + v1.w*kw4.w;
                float ss1 = v1.x*v1.x + v1.y*v1.y + v1.z*v1.z + v1.w*v1.w;
                #pragma unroll
                for (int o = 16; o; o >>= 1) {
                    dr0 += __shfl_xor_sync(0xffffffffu, dr0, o);
                    dw0 += __shfl_xor_sync(0xffffffffu, dw0, o);
                    ss0 += __shfl_xor_sync(0xffffffffu, ss0, o);
                    dr1 += __shfl_xor_sync(0xffffffffu, dr1, o);
                    dw1 += __shfl_xor_sync(0xffffffffu, dw1, o);
                    ss1 += __shfl_xor_sync(0xffffffffu, ss1, o);
                }
                if (lane == 0) {
                    s_dr[n0] = dr0; s_dw[n0] = dw0; s_nrm[n0] = sqrtf(ss0);
                    s_dr[n1] = dr1; s_dw[n1] = dw1; s_nrm[n1] = sqrtf(ss1);
                }
            }
        }
        __syncthreads();

        int n = tid;
        bool act = (tid < NS);

        // ===== read attention (warp0-reduced softmax) =====
        {
            float c = 0.f;
            if (act) {
                c = s_par[0] * s_dr[n] / (s_nrm[n] * s_kn[0] + EPSF);
                s_dr[n] = c;                      // overwrite dr with logits
            }
            __syncthreads();
            if (wid == 0) {                       // warp 0: max + exp-sum in one pass
                float vals[16], m = -INFINITY;
                #pragma unroll
                for (int k = 0; k < 16; k++) { vals[k] = s_dr[lane + k*32]; m = fmaxf(m, vals[k]); }
                #pragma unroll
                for (int o = 16; o; o >>= 1) m = fmaxf(m, __shfl_xor_sync(0xffffffffu, m, o));
                float se = 0.f;
                #pragma unroll
                for (int k = 0; k < 16; k++) se += __expf(vals[k] - m);
                #pragma unroll
                for (int o = 16; o; o >>= 1) se += __shfl_xor_sync(0xffffffffu, se, o);
                if (lane == 0) { s_red[0] = m; s_red[1] = se; }
            }
            __syncthreads();
            if (act) {
                float wc = __expf(c - s_red[0]) / s_red[1];
                float gr = s_par[1];
                s_wg[n] = gr * wc + (1.f - gr) * s_wprev[n];
            }
            __syncthreads();
            float w = 0.f;
            if (act) {
                float wt = s_par[2] * s_wg[(n+1) & (NS-1)] + s_par[3] * s_wg[n]
                         + s_par[4] * s_wg[(n-1) & (NS-1)];
                w = __powf(wt, s_par[5]);
                scratch[n] = w;
            }
            __syncthreads();
            if (wid == 0) {
                float sw = 0.f;
                #pragma unroll
                for (int k = 0; k < 16; k++) sw += scratch[lane + k*32];
                #pragma unroll
                for (int o = 16; o; o >>= 1) sw += __shfl_xor_sync(0xffffffffu, sw, o);
                if (lane == 0) s_red[0] = sw;
            }
            __syncthreads();
            if (act) s_wr[n] = w / (s_red[0] + EPSF);
        }
        __syncthreads();

        // ===== write attention (w_prev = w_r) =====
        {
            float c = 0.f;
            if (act) {
                c = s_par[6] * s_dw[n] / (s_nrm[n] * s_kn[1] + EPSF);
                s_dw[n] = c;
            }
            __syncthreads();
            if (wid == 0) {
                float vals[16], m = -INFINITY;
                #pragma unroll
                for (int k = 0; k < 16; k++) { vals[k] = s_dw[lane + k*32]; m = fmaxf(m, vals[k]); }
                #pragma unroll
                for (int o = 16; o; o >>= 1) m = fmaxf(m, __shfl_xor_sync(0xffffffffu, m, o));
                float se = 0.f;
                #pragma unroll
                for (int k = 0; k < 16; k++) se += __expf(vals[k] - m);
                #pragma unroll
                for (int o = 16; o; o >>= 1) se += __shfl_xor_sync(0xffffffffu, se, o);
                if (lane == 0) { s_red[0] = m; s_red[1] = se; }
            }
            __syncthreads();
            if (act) {
                float wc = __expf(c - s_red[0]) / s_red[1];
                float gw = s_par[7];
                s_wg[n] = gw * wc + (1.f - gw) * s_wr[n];
            }
            __syncthreads();
            float w = 0.f;
            if (act) {
                float wt = s_par[8] * s_wg[(n+1) & (NS-1)] + s_par[9] * s_wg[n]
                         + s_par[10] * s_wg[(n-1) & (NS-1)];
                w = __powf(wt, s_par[11]);
                scratch[n] = w;
            }
            __syncthreads();
            if (wid == 0) {
                float sw = 0.f;
                #pragma unroll
                for (int k = 0; k < 16; k++) sw += scratch[lane + k*32];
                #pragma unroll
                for (int o = 16; o; o >>= 1) sw += __shfl_xor_sync(0xffffffffu, sw, o);
                if (lane == 0) s_red[0] = sw;
            }
            __syncthreads();
            if (act) {
                float ww = w / (s_red[0] + EPSF);
                s_ww[n] = ww;
                s_wprev[n] = ww;
            }
        }
        __syncthreads();

        // ===== phase F: r = w_r . mem(old) + mem update; thread=col j, 8 n-chunks =====
        {
            int j = tid & 127, ch = tid >> 7;       // 8 chunks of 64 slots
            float e_j = osm[268 + j];
            float a_j = osm[396 + j];
            float* mb = g_mem + (size_t)b*NS*DH;
            float racc = 0.f;
            int nb = ch * 64;
            #pragma unroll 8
            for (int q = 0; q < 64; q++) {
                int nn = nb + q;
                float v = mb[nn*DH + j];
                racc = fmaf(s_wr[nn], v, racc);
                float wwn = s_ww[nn];
                mb[nn*DH + j] = fmaf(wwn, fmaf(-e_j, v, a_j), v);
            }
            scratch[ch*DH + j] = racc;
        }
        __syncthreads();
        if (tid < DH) {
            float r = 0.f;
            #pragma unroll
            for (int ch = 0; ch < 8; ch++) r += scratch[ch*DH + tid];
            s_r[tid] = r;
            g_rall[(t*BS + b)*DH + tid] = r;
            s_h[tid] = s_hn[tid];
        }
        __syncthreads();
    }
}

// ---------------- deferred output GEMM: 256 blocks x 256 thr, 16 rows/block ----------------
__global__ __launch_bounds__(256)
void y_kernel(const float* __restrict__ Wout,
              const float* __restrict__ bout,
              float* __restrict__ out) {
    __shared__ float sh[16][DH], sr[16][DH];
    int r0  = blockIdx.x * 16;         // row = t*BS + b
    int tid = threadIdx.x;
    for (int idx = tid; idx < 16*DH; idx += 256) {
        int rr = idx >> 7, i = idx & 127;
        sh[rr][i] = g_hall[(r0 + rr)*DH + i];
        sr[rr][i] = g_rall[(r0 + rr)*DH + i];
    }
    __syncthreads();
    int j = tid & 127, rg = tid >> 7;  // rg in {0,1}
    float acc[8];
    #pragma unroll
    for (int rr = 0; rr < 8; rr++) acc[rr] = 0.f;
    #pragma unroll 4
    for (int i = 0; i < DH; i++) {
        float w1 = Wout[i * DH + j];
        float w2 = Wout[(DH + i) * DH + j];
        #pragma unroll
        for (int rr = 0; rr < 8; rr++)
            acc[rr] += sh[rg*8 + rr][i] * w1 + sr[rg*8 + rr][i] * w2;
    }
    float bb = bout[j];
    #pragma unroll
    for (int rr = 0; rr < 8; rr++) {
        int row = r0 + rg*8 + rr;          // row = t*BS + b
        int tt = row >> 7, bb2 = row & 127;
        out[(bb2 * T + tt) * DH + j] = acc[rr] + bb;
    }
}

// ---------------- launch ----------------
extern "C" void kernel_launch(void* const* d_in, const int* in_sizes, int n_in,
                              void* d_out, int out_size) {
    const float* x    = (const float*)d_in[0];
    const float* Wxh  = (const float*)d_in[1];
    const float* Whh  = (const float*)d_in[2];
    const float* Wrh  = (const float*)d_in[3];
    const float* bh   = (const float*)d_in[4];
    const float* Wout = (const float*)d_in[5];
    const float* bout = (const float*)d_in[6];
    const float* Wr   = (const float*)d_in[7];
    const float* br   = (const float*)d_in[8];
    const float* Ww   = (const float*)d_in[9];
    const float* bw   = (const float*)d_in[10];
    float* out = (float*)d_out;

    // opt-in to large dynamic smem (non-stream API; graph-capture safe, idempotent)
    cudaFuncSetAttribute(seq_kernel, cudaFuncAttributeMaxDynamicSharedMemorySize, DYN_BYTES);

    init_kernel<<<1024, 256>>>();
    xw_kernel<<<(BS*T)/16, 256>>>(x, Wxh, bh);
    seq_kernel<<<BS, NT, DYN_BYTES>>>(Whh, Wrh, Wr, br, Ww, bw);
    y_kernel<<<(BS*T)/16, 256>>>(Wout, bout, out);
}